// round 17
// baseline (speedup 1.0000x reference)
#include <cuda_runtime.h>
#include <cuda_bf16.h>
#include <cuda_fp16.h>
#include <cstdint>
#include <math.h>

#define S_SYS 32
#define N_ATOM 512
#define F_DIM 256
#define R_EXCL 5.0f

// Scratch (__device__ globals; allocation-free rule).
__device__ __align__(16) uint16_t g_q16[(size_t)S_SYS * F_DIM * N_ATOM]; // 8 MB q^T fp16

// ---------------------------------------------------------------------------
// helpers
// ---------------------------------------------------------------------------
__device__ __forceinline__ uint32_t smem_u32(const void* p) {
    uint32_t a;
    asm("{ .reg .u64 t; cvta.to.shared.u64 t, %1; cvt.u32.u64 %0, t; }" : "=r"(a) : "l"(p));
    return a;
}
__device__ __forceinline__ void mma_f16(float* c, const uint32_t* a, uint32_t b0, uint32_t b1) {
    asm volatile(
        "mma.sync.aligned.m16n8k16.row.col.f32.f16.f16.f32 "
        "{%0,%1,%2,%3}, {%4,%5,%6,%7}, {%8,%9}, {%0,%1,%2,%3};"
        : "+f"(c[0]), "+f"(c[1]), "+f"(c[2]), "+f"(c[3])
        : "r"(a[0]), "r"(a[1]), "r"(a[2]), "r"(a[3]), "r"(b0), "r"(b1));
}
// f16 accumulator variant: D/C are 2 regs (4 halves)
__device__ __forceinline__ void mma_f16acc(uint32_t* c, const uint32_t* a, uint32_t b0, uint32_t b1) {
    asm volatile(
        "mma.sync.aligned.m16n8k16.row.col.f16.f16.f16.f16 "
        "{%0,%1}, {%2,%3,%4,%5}, {%6,%7}, {%0,%1};"
        : "+r"(c[0]), "+r"(c[1])
        : "r"(a[0]), "r"(a[1]), "r"(a[2]), "r"(a[3]), "r"(b0), "r"(b1));
}
__device__ __forceinline__ void ldsm4(uint32_t* r, uint32_t addr) {
    asm volatile("ldmatrix.sync.aligned.m8n8.x4.shared.b16 {%0,%1,%2,%3}, [%4];"
                 : "=r"(r[0]), "=r"(r[1]), "=r"(r[2]), "=r"(r[3]) : "r"(addr));
}
#define CP_ASYNC16(dst, src) \
    asm volatile("cp.async.cg.shared.global [%0], [%1], 16;" :: "r"(dst), "l"(src))
#define CP_COMMIT() asm volatile("cp.async.commit_group;" ::: "memory")
#define CP_WAIT(n)  asm volatile("cp.async.wait_group %0;" :: "n"(n) : "memory")

// ===========================================================================
// GEMM1 (unchanged from R14): qT[s][f][a] = sum_k W[f,k]*feat[a,k] + b[f]
// single fp16, f32 accum. BM=128, BN=128, BK=32, 256 threads, 2 CTAs/SM.
// ===========================================================================
#define G1_RAWA(st) ((st) * 32768)
#define G1_RAWB(st) ((st) * 32768 + 16384)
#define G1_AH 65536
#define G1_BH 75776
#define G1_SMEM 86016

__global__ __launch_bounds__(256, 2) void gemm1_mma(
    const float* __restrict__ W, const float* __restrict__ feat,
    const float* __restrict__ bias,
    uint16_t* __restrict__ q16)
{
    extern __shared__ char sm[];
    const int t = threadIdx.x, lane = t & 31, w = t >> 5;
    const int wm = (w & 3) * 32, wn = (w >> 2) * 64;
    const int aB = blockIdx.x * 128, fB = blockIdx.y * 128;
    const uint32_t sb = smem_u32(sm);

    const char* Ag = (const char*)(W + (size_t)fB * F_DIM);
    const char* Bg = (const char*)(feat + (size_t)aB * F_DIM);

    float c[2][8][4] = {};
    const int mrow = (lane & 7) + ((lane >> 3) & 1) * 8;
    const int kb   = (lane >> 4) * 16;
    uint32_t arow[2], brow[4];
    #pragma unroll
    for (int mt = 0; mt < 2; ++mt) arow[mt] = (uint32_t)((wm + mt * 16 + mrow) * 80 + kb);
    #pragma unroll
    for (int np = 0; np < 4; ++np) brow[np] = (uint32_t)((wn + np * 16 + mrow) * 80 + kb);

    auto load_raw = [&](int ch, int st) {
        #pragma unroll
        for (int j = 0; j < 8; ++j) {
            int u = t + j * 256;
            if (u < 1024) {
                int row = u >> 3, sg = u & 7;
                CP_ASYNC16(sb + G1_RAWA(st) + (uint32_t)(row * 128 + sg * 16),
                           Ag + (size_t)row * 1024 + ch * 128 + sg * 16);
            } else {
                int u2 = u - 1024, row = u2 >> 3, sg = u2 & 7;
                CP_ASYNC16(sb + G1_RAWB(st) + (uint32_t)(row * 128 + sg * 16),
                           Bg + (size_t)row * 1024 + ch * 128 + sg * 16);
            }
        }
        CP_COMMIT();
    };

    load_raw(0, 0);

    for (int ch = 0; ch < 8; ++ch) {
        if (ch + 1 < 8) {
            load_raw(ch + 1, (ch + 1) & 1);
            CP_WAIT(1);
        } else {
            CP_WAIT(0);
        }
        __syncthreads();

        {
            const char* rawA = sm + G1_RAWA(ch & 1);
            const char* rawB = sm + G1_RAWB(ch & 1);
            #pragma unroll
            for (int j = 0; j < 8; ++j) {
                int u = t + j * 256;
                const char* src;
                uint32_t dst;
                int row, kq;
                if (u < 1024) {
                    row = u >> 3; kq = u & 7;
                    src = rawA + row * 128 + kq * 16;
                    dst = (uint32_t)G1_AH;
                } else {
                    int u2 = u - 1024; row = u2 >> 3; kq = u2 & 7;
                    src = rawB + row * 128 + kq * 16;
                    dst = (uint32_t)G1_BH;
                }
                float4 x = *(const float4*)src;
                __half2 h01 = __floats2half2_rn(x.x, x.y);
                __half2 h23 = __floats2half2_rn(x.z, x.w);
                uint32_t off = (uint32_t)(row * 80 + kq * 8);
                *(uint2*)(sm + dst + off) =
                    make_uint2(*(uint32_t*)&h01, *(uint32_t*)&h23);
            }
        }
        __syncthreads();

        #pragma unroll
        for (int ks = 0; ks < 2; ++ks) {
            const uint32_t col = (uint32_t)(ks * 32);
            uint32_t ah[2][4], bh[4][4];
            #pragma unroll
            for (int mt = 0; mt < 2; ++mt) ldsm4(ah[mt], sb + G1_AH + arow[mt] + col);
            #pragma unroll
            for (int np = 0; np < 4; ++np) ldsm4(bh[np], sb + G1_BH + brow[np] + col);
            #pragma unroll
            for (int mt = 0; mt < 2; ++mt)
                #pragma unroll
                for (int nt = 0; nt < 8; ++nt)
                    mma_f16(c[mt][nt], ah[mt], bh[nt >> 1][nt & 1], bh[nt >> 1][(nt & 1) + 2]);
        }
    }

    const int sID = blockIdx.x >> 2;
    const int aLoc0 = (blockIdx.x & 3) * 128;
    uint16_t* qh16 = q16 + (size_t)sID * F_DIM * N_ATOM;
    #pragma unroll
    for (int mt = 0; mt < 2; ++mt) {
        #pragma unroll
        for (int nt = 0; nt < 8; ++nt) {
            const int fg = fB + wm + mt * 16 + (lane >> 2);
            const int ag = aLoc0 + wn + nt * 8 + (lane & 3) * 2;
            float* cf = c[mt][nt];
            float bv0 = bias[fg], bv1 = bias[fg + 8];
            __half2 p01 = __floats2half2_rn(cf[0] + bv0, cf[1] + bv0);
            __half2 p23 = __floats2half2_rn(cf[2] + bv1, cf[3] + bv1);
            *(__half2*)(qh16 + (size_t)fg * N_ATOM + ag) = p01;
            *(__half2*)(qh16 + (size_t)(fg + 8) * N_ATOM + ag) = p23;
        }
    }
}

// ===========================================================================
// GEMM2 fused: out[s,m,f] = 0.5*(sum_j v(m,j) q[j,f])*q[m,f]
// v single fp16 on-the-fly, q single fp16. f16 ACCUM within each 64-k chunk,
// promoted to f32 per chunk (n-tile halved to bound register pressure).
// BM=128, BN=256, BK=64. 512 threads, warp tile 32x64 (4m x 4n warps).
// smem: pos@0(6K) | V @6144 (2 x 18432) | Q @43008 (3 x 36864) = 153600
// ===========================================================================
#define G2_VS(st) (6144 + (st) * 18432)
#define G2_QS(st) (43008 + (st) * 36864)
#define G2_SMEM 153600

__device__ __forceinline__ void gemm2_step(
    uint32_t vbase, uint32_t qbase,
    const uint32_t arow[2], const uint32_t brow[4], float c32[2][8][4])
{
    // two n-halves: nt 0..3 then 4..7, each accumulated in f16 over 4 ks
    #pragma unroll
    for (int h = 0; h < 2; ++h) {
        uint32_t c16[2][4][2] = {};
        #pragma unroll
        for (int ks = 0; ks < 4; ++ks) {
            const uint32_t col = (uint32_t)(ks * 32);
            uint32_t ah[2][4], bh[2][4];
            #pragma unroll
            for (int mt = 0; mt < 2; ++mt) ldsm4(ah[mt], vbase + arow[mt] + col);
            #pragma unroll
            for (int np = 0; np < 2; ++np) ldsm4(bh[np], qbase + brow[h * 2 + np] + col);
            #pragma unroll
            for (int mt = 0; mt < 2; ++mt)
                #pragma unroll
                for (int nt = 0; nt < 4; ++nt)
                    mma_f16acc(c16[mt][nt], ah[mt],
                               bh[nt >> 1][nt & 1], bh[nt >> 1][(nt & 1) + 2]);
        }
        // promote chunk partials to f32
        #pragma unroll
        for (int mt = 0; mt < 2; ++mt)
            #pragma unroll
            for (int nt = 0; nt < 4; ++nt) {
                float* cf = c32[mt][h * 4 + nt];
                float2 f0 = __half22float2(*(__half2*)&c16[mt][nt][0]);
                float2 f1 = __half22float2(*(__half2*)&c16[mt][nt][1]);
                cf[0] += f0.x; cf[1] += f0.y;
                cf[2] += f1.x; cf[3] += f1.y;
            }
    }
}

__global__ __launch_bounds__(512) void gemm2_fused(
    const float* __restrict__ pos,
    const uint16_t* __restrict__ q16,
    float* __restrict__ out)
{
    extern __shared__ char sm[];
    const int t = threadIdx.x, lane = t & 31, w = t >> 5;
    const int wm = (w & 3) * 32, wn = (w >> 2) * 64;
    const int m0 = blockIdx.x * 128, s = blockIdx.y;
    const uint32_t sb = smem_u32(sm);

    float* sx = (float*)(sm);
    float* sy = (float*)(sm + 2048);
    float* sz = (float*)(sm + 4096);

    const float* ps = pos + (size_t)s * N_ATOM * 3;
    {
        float3 p = *(const float3*)(ps + t * 3);
        sx[t] = p.x; sy[t] = p.y; sz[t] = p.z;
    }
    __syncthreads();

    const int irow = t >> 2;            // 0..127 (v row)
    const int jq   = (t & 3);           // 16-j group within 64-chunk
    const int ig   = m0 + irow;
    const float xi = sx[ig], yi = sy[ig], zi = sz[ig];
    const float cc = 3.14159265358979323846f / R_EXCL;

    const char* Bq = (const char*)(q16 + (size_t)s * F_DIM * N_ATOM);  // 1024B row stride

    float c[2][8][4] = {};
    const int mrow = (lane & 7) + ((lane >> 3) & 1) * 8;
    const int kb   = (lane >> 4) * 16;
    uint32_t arow[2], brow[4];
    #pragma unroll
    for (int mt = 0; mt < 2; ++mt) arow[mt] = (uint32_t)((wm + mt * 16 + mrow) * 144 + kb);
    #pragma unroll
    for (int np = 0; np < 4; ++np) brow[np] = (uint32_t)((wn + np * 16 + mrow) * 144 + kb);

    auto produce_v = [&](int ch, int st) {
        const int jbase = ch * 64 + jq * 16;
        __half2 hq[8];
        #pragma unroll
        for (int p = 0; p < 4; ++p) {
            const int j0 = jbase + p * 4;
            float4 x4 = *(const float4*)(sx + j0);
            float4 y4 = *(const float4*)(sy + j0);
            float4 z4 = *(const float4*)(sz + j0);
            float vv[4];
            #pragma unroll
            for (int e = 0; e < 4; ++e) {
                float dx = xi - ((const float*)&x4)[e];
                float dy = yi - ((const float*)&y4)[e];
                float dz = zi - ((const float*)&z4)[e];
                float d2 = fmaf(dx, dx, fmaf(dy, dy, dz * dz));
                float val = 0.0f;
                if (j0 + e != ig) {
                    float inv = rsqrtf(d2);
                    float d = d2 * inv;
                    float fcut = (d < R_EXCL) ? 0.5f * (1.0f + __cosf(cc * d)) : 0.0f;
                    val = (1.0f - fcut) * inv;
                }
                vv[e] = val;
            }
            hq[p * 2]     = __floats2half2_rn(vv[0], vv[1]);
            hq[p * 2 + 1] = __floats2half2_rn(vv[2], vv[3]);
        }
        uint32_t off = (uint32_t)(G2_VS(st) + irow * 144 + jq * 32);
        *(uint4*)(sm + off)      = ((uint4*)hq)[0];
        *(uint4*)(sm + off + 16) = ((uint4*)hq)[1];
    };
    auto load_q = [&](int ch, int st) {
        #pragma unroll
        for (int j = 0; j < 4; ++j) {
            int u = t + j * 512;
            int row = u >> 3, sg = u & 7;
            const char* src = Bq + (size_t)row * 1024 + ch * 128 + sg * 16;
            CP_ASYNC16(sb + (uint32_t)(G2_QS(st) + row * 144 + sg * 16), src);
        }
        CP_COMMIT();
    };

    produce_v(0, 0);
    load_q(0, 0);
    load_q(1, 1);

    for (int ch = 0; ch < 8; ++ch) {
        __syncthreads();
        if (ch + 1 < 8) produce_v(ch + 1, (ch + 1) & 1);
        if (ch + 2 < 8) {
            load_q(ch + 2, (ch + 2) % 3);
            CP_WAIT(2);
        } else if (ch + 1 < 8) {
            CP_WAIT(1);
        } else {
            CP_WAIT(0);
        }
        gemm2_step(sb + (uint32_t)G2_VS(ch & 1), sb + (uint32_t)G2_QS(ch % 3), arow, brow, c);
    }
    __syncthreads();

    // Epilogue: stage q16[m,f] tile as fp32 in 2 f-halves (smem stride 132)
    float* sq = (float*)sm;
    float* outB = out + ((size_t)(s * N_ATOM) + m0) * F_DIM;
    #pragma unroll
    for (int h = 0; h < 2; ++h) {
        #pragma unroll
        for (int j = 0; j < 8; ++j) {
            int u = t + j * 512;
            int row = u >> 5, un = u & 31;
            uint2 hr = *(const uint2*)(Bq + (size_t)(h * 128 + row) * 1024
                                       + (size_t)(m0 + un * 4) * 2);
            float2 f0 = __half22float2(*(__half2*)&hr.x);
            float2 f1 = __half22float2(*(__half2*)&hr.y);
            *(float4*)(sq + row * 132 + un * 4) = make_float4(f0.x, f0.y, f1.x, f1.y);
        }
        __syncthreads();
        if ((wn >> 7) == h) {
            #pragma unroll
            for (int mt = 0; mt < 2; ++mt) {
                #pragma unroll
                for (int nt = 0; nt < 8; ++nt) {
                    const int ml = wm + mt * 16 + (lane >> 2);
                    const int fg = wn + nt * 8 + (lane & 3) * 2;
                    const int fl = fg - h * 128;
                    float* cf = c[mt][nt];
                    float q00 = sq[fl * 132 + ml], q01 = sq[(fl + 1) * 132 + ml];
                    float2 o0 = make_float2(0.5f * cf[0] * q00, 0.5f * cf[1] * q01);
                    *(float2*)(outB + (size_t)ml * F_DIM + fg) = o0;
                    float q10 = sq[fl * 132 + ml + 8], q11 = sq[(fl + 1) * 132 + ml + 8];
                    float2 o1 = make_float2(0.5f * cf[2] * q10, 0.5f * cf[3] * q11);
                    *(float2*)(outB + (size_t)(ml + 8) * F_DIM + fg) = o1;
                }
            }
        }
        __syncthreads();
    }
}

// ---------------------------------------------------------------------------
extern "C" void kernel_launch(void* const* d_in, const int* in_sizes, int n_in,
                              void* d_out, int out_size)
{
    const float* positions = (const float*)d_in[0]; // [32, 512, 3]
    const float* features  = (const float*)d_in[1]; // [16384, 256]
    const float* W         = (const float*)d_in[2]; // [256, 256]
    const float* b         = (const float*)d_in[3]; // [256]
    float* out             = (float*)d_out;         // [16384, 256]

    uint16_t* q16;
    cudaGetSymbolAddress((void**)&q16, g_q16);

    cudaFuncSetAttribute(gemm1_mma, cudaFuncAttributeMaxDynamicSharedMemorySize, G1_SMEM);
    cudaFuncSetAttribute(gemm2_fused, cudaFuncAttributeMaxDynamicSharedMemorySize, G2_SMEM);

    // q^T = W @ feat^T + b  (single fp16, f32 accum), 256 CTAs
    gemm1_mma<<<dim3(128, 2), 256, G1_SMEM>>>(W, features, b, q16);
    // out = 0.5 * (v @ q) * q, v on-the-fly; f16-accum probe, 128 CTAs
    gemm2_fused<<<dim3(4, 32), 512, G2_SMEM>>>(positions, q16, out);
}